// round 9
// baseline (speedup 1.0000x reference)
#include <cuda_runtime.h>
#include <cuda_fp16.h>
#include <stdint.h>

#define NROWS 8192
#define INP   512
#define NOUT  128
#define SLOPE 0.2f

// ---------------- device scratch ----------------
__device__ float  g_f1[NROWS];
__device__ float  g_f2[NROWS];
__device__ float  g_A[NROWS];
__device__ float  g_C[NROWS];
__device__ uint4  g_UVT2[2 * 128 * 1024];       // 4 MB: {U,V} fp16 x 128 chunks x 16KB pre-swizzled B^T tiles
__device__ uint4  g_ZT[128 * 64];               // per chunk: 8 rows x 64 j fp16 (u, v, zero...)
__device__ float  g_pp[2 * NROWS * NOUT];
__device__ float  g_pn[2 * NROWS * NOUT];
__device__ float  g_zu[2 * NROWS];
__device__ float  g_zv[2 * NROWS];
__device__ unsigned int g_cnt;

// ---------------- helpers ----------------
__device__ __forceinline__ uint32_t smem_u32(const void* p) {
    uint32_t r;
    asm("{ .reg .u64 t; cvta.to.shared.u64 t, %1; cvt.u32.u64 %0, t; }" : "=r"(r) : "l"(p));
    return r;
}
#define SW128(x) ((x) ^ (((x) >> 3) & 0x70))

#define LDSM_X4(r0, r1, r2, r3, addr) \
    asm volatile("ldmatrix.sync.aligned.m8n8.x4.shared.b16 {%0,%1,%2,%3}, [%4];" \
        : "=r"(r0), "=r"(r1), "=r"(r2), "=r"(r3) : "r"(addr))

#define MMA16816(d, a0, a1, a2, a3, b0, b1) \
    asm volatile("mma.sync.aligned.m16n8k16.row.col.f32.f16.f16.f32 " \
        "{%0,%1,%2,%3},{%4,%5,%6,%7},{%8,%9},{%0,%1,%2,%3};" \
        : "+f"((d)[0]), "+f"((d)[1]), "+f"((d)[2]), "+f"((d)[3]) \
        : "r"(a0), "r"(a1), "r"(a2), "r"(a3), "r"(b0), "r"(b1))

__device__ __forceinline__ void cp_async16(uint32_t dst, const void* src) {
    asm volatile("cp.async.cg.shared.global [%0], [%1], 16;" :: "r"(dst), "l"(src) : "memory");
}
#define CP_COMMIT() asm volatile("cp.async.commit_group;" ::: "memory")
#define CP_WAIT2()  asm volatile("cp.async.wait_group 2;" ::: "memory")
#define CP_WAIT1()  asm volatile("cp.async.wait_group 1;" ::: "memory")

__device__ __forceinline__ unsigned pack_f16x2(float lo, float hi) {
    unsigned r;
    asm("cvt.rn.f16x2.f32 %0, %1, %2;" : "=r"(r) : "f"(hi), "f"(lo));
    return r;
}
__device__ __forceinline__ unsigned prmt(unsigned a, unsigned b, unsigned s) {
    unsigned r;
    asm("prmt.b32 %0, %1, %2, %3;" : "=r"(r) : "r"(a), "r"(b), "r"(s));
    return r;
}

// ============ kA: Wh GEMM + features + UVT/ZT production (128 blocks) ============
__global__ __launch_bounds__(256) void kA(const float* __restrict__ h, const float* __restrict__ W,
                                          const float* __restrict__ a) {
    __shared__ float hs[64][33];
    __shared__ float Ws[32][128];
    const int t  = threadIdx.x;
    const int i0 = blockIdx.x * 64;
    const int tx = t & 31;
    const int ty = t >> 5;

    float acc[8][4];
#pragma unroll
    for (int r = 0; r < 8; r++)
#pragma unroll
        for (int c = 0; c < 4; c++) acc[r][c] = 0.f;

    for (int k0 = 0; k0 < INP; k0 += 32) {
#pragma unroll
        for (int p = 0; p < 2; p++) {
            int u = t + p * 256;
            int r = u >> 3, kc = (u & 7) * 4;
            float4 hv = *(const float4*)(h + (size_t)(i0 + r) * INP + k0 + kc);
            hs[r][kc] = hv.x; hs[r][kc + 1] = hv.y; hs[r][kc + 2] = hv.z; hs[r][kc + 3] = hv.w;
        }
#pragma unroll
        for (int p = 0; p < 4; p++) {
            int u = t + p * 256;
            int kr = u >> 5, cc = (u & 31) * 4;
            *(float4*)&Ws[kr][cc] = *(const float4*)(W + (size_t)(k0 + kr) * NOUT + cc);
        }
        __syncthreads();
#pragma unroll
        for (int kk = 0; kk < 32; kk++) {
            float4 bv = *(float4*)&Ws[kk][tx * 4];
#pragma unroll
            for (int r = 0; r < 8; r++) {
                float av = hs[ty * 8 + r][kk];
                acc[r][0] += av * bv.x; acc[r][1] += av * bv.y;
                acc[r][2] += av * bv.z; acc[r][3] += av * bv.w;
            }
        }
        __syncthreads();
    }

    float4 a1 = __ldg((const float4*)(a + tx * 4));
    float4 a2 = __ldg((const float4*)(a + 128 + tx * 4));
    float uu[8], vv[8];
#pragma unroll
    for (int r = 0; r < 8; r++) {
        float s1 = acc[r][0] * a1.x + acc[r][1] * a1.y + acc[r][2] * a1.z + acc[r][3] * a1.w;
        float s2 = acc[r][0] * a2.x + acc[r][1] * a2.y + acc[r][2] * a2.z + acc[r][3] * a2.w;
#pragma unroll
        for (int off = 16; off > 0; off >>= 1) {
            s1 += __shfl_xor_sync(0xffffffffu, s1, off);
            s2 += __shfl_xor_sync(0xffffffffu, s2, off);
        }
        uu[r] = expf(s2);
        vv[r] = expf(SLOPE * s2);
        if (tx == r) {
            int j = i0 + ty * 8 + r;
            g_f1[j] = s1;
            g_f2[j] = s2;
            g_A[j]  = expf(s1);
            g_C[j]  = expf(SLOPE * s1);
        }
    }

    const int jbase = ty * 8;
    char* base = (char*)g_UVT2 + (size_t)blockIdx.x * 16384;
#pragma unroll
    for (int rp = 0; rp < 4; rp++) {
#pragma unroll
        for (int c = 0; c < 4; c++) {
            float U0 = uu[2 * rp] * acc[2 * rp][c],     U1 = uu[2 * rp + 1] * acc[2 * rp + 1][c];
            float V0 = vv[2 * rp] * acc[2 * rp][c],     V1 = vv[2 * rp + 1] * acc[2 * rp + 1][c];
            unsigned off = SW128((unsigned)((tx * 4 + c) * 128 + (jbase + 2 * rp) * 2));
            *(unsigned*)(base + off)            = pack_f16x2(U0, U1);
            *(unsigned*)(base + 2097152u + off) = pack_f16x2(V0, V1);
        }
    }

    {
        char* zb = (char*)g_ZT + (size_t)blockIdx.x * 1024;
        int rsel = tx & 7;
        float us = uu[0], vs = vv[0];
#pragma unroll
        for (int r = 1; r < 8; r++) if (rsel == r) { us = uu[r]; vs = vv[r]; }
        int n = tx >> 3;
        if (n < 2) {
            float val = (n == 0) ? us : vs;
            unsigned off = (unsigned)(n * 128) + (((unsigned)((jbase + rsel) * 2)) ^ ((unsigned)n << 4));
            *(__half*)(zb + off) = __float2half(val);
        }
        if (t < 192) {
            int zn = 2 + (t >> 5);
            unsigned zoff = (unsigned)(zn * 128) + ((((unsigned)(t & 31)) * 4u) ^ ((unsigned)(zn & 7) << 4));
            *(unsigned*)(zb + zoff) = 0u;
        }
    }
}

// ============ K4: fp16 HMMA masked GEMMs + Z streams + raw-adj streaming + combine ============
#define MASKBUF   32768
#define BTILE     16384
#define ZTB       1024
#define BBUF      (2 * BTILE + ZTB)              // 33792
#define ADJBUF    32768
#define DYNSMEM   (2 * MASKBUF + 2 * BBUF + 2 * ADJBUF)   // 198656

__global__ void __launch_bounds__(512, 1) k4_hmma(const int* __restrict__ adj, float* __restrict__ out) {
    extern __shared__ __align__(16) char dyn[];
    __shared__ float s_f1[128];
    __shared__ __align__(16) float s_f2[4096];

    const int tid  = threadIdx.x;
    const int wid  = tid >> 5;
    const int lane = tid & 31;
    const int rt = blockIdx.x >> 1;
    const int hh = blockIdx.x & 1;
    const int i0 = rt << 7;
    const int j0 = hh << 12;

    const uint32_t dbase  = smem_u32(dyn);
    const uint32_t bbuf_u = dbase + 2u * MASKBUF;
    const uint32_t adj_u  = bbuf_u + 2u * BBUF;

    if (tid < 128) s_f1[tid] = g_f1[i0 + tid];
    for (int q = tid; q < 4096; q += 512) s_f2[q] = g_f2[j0 + q];
    __syncthreads();

    float dp[2][4][4], dn[2][4][4];
    float dzp[2][4], dzn[2][4];
#pragma unroll
    for (int mt = 0; mt < 2; mt++) {
#pragma unroll
        for (int nt = 0; nt < 4; nt++)
#pragma unroll
            for (int r = 0; r < 4; r++) { dp[mt][nt][r] = 0.f; dn[mt][nt][r] = 0.f; }
#pragma unroll
        for (int r = 0; r < 4; r++) { dzp[mt][r] = 0.f; dzn[mt][r] = 0.f; }
    }

    const int warp_m = wid >> 2;
    const int warp_n = wid & 3;
    const bool diag = (warp_m == warp_n);
    const int ib = warp_m << 5;
    const int cb = warp_n << 5;

    const int ri0 = ib + (lane & 15);
    const int ri1 = ri0 + 16;
    const uint32_t arow0 = (uint32_t)ri0 * 128u, asw0 = (uint32_t)(ri0 & 7) << 4;
    const uint32_t arow1 = (uint32_t)ri1 * 128u, asw1 = (uint32_t)(ri1 & 7) << 4;
    const uint32_t akh   = (uint32_t)(lane >> 4) << 4;
    const int cr = cb + lane;
    const uint32_t brow = (uint32_t)cr * 128u, bsw = (uint32_t)(cr & 7) << 4;

    const uint32_t zn   = (uint32_t)(lane >> 2);
    const uint32_t zsw  = (zn & 7u) << 4;
    const uint32_t zrow = 2u * BTILE + zn * 128u;
    const uint32_t zkb  = ((uint32_t)(lane & 3)) << 2;

    // ---- adj prefetch: chunk c -> slot c&1. Each thread fetches ITS OWN 64B
    //      (row tid>>2, 16 ints at col (tid&3)*16), seg-major layout [seg][tid]
    //      so later LDS.128 reads are conflict-free. Reader == issuer: no bar needed.
    const int*     adj_src0 = adj + (size_t)(i0 + (tid >> 2)) * NROWS + j0 + ((tid & 3) << 4);
    const uint32_t adj_dst0 = adj_u + (uint32_t)tid * 16u;
    auto prefetch_adj = [&](int c) {
        const uint32_t dst = adj_dst0 + (uint32_t)(c & 1) * ADJBUF;
        const int* src = adj_src0 + (c << 6);
#pragma unroll
        for (int k = 0; k < 4; k++)
            cp_async16(dst + (uint32_t)k * 8192u, src + k * 4);
    };

    // ---- mask tile builder (chunk c -> buffer mb); adj from own SMEM region ----
    auto build_masks = [&](int c, int mb) {
        char* mdst = dyn + mb * MASKBUF;
        const int tch = c << 6;
        const char* asl = dyn + 2 * MASKBUF + 2 * BBUF + (c & 1) * ADJBUF + tid * 16;
        const int i = tid >> 2;
        const float thr = -s_f1[i];
        const uint32_t rb  = (uint32_t)i * 128u;
        const uint32_t rsw = (uint32_t)(i & 7) << 4;
#pragma unroll
        for (int un = 0; un < 2; un++) {
            const int jl = ((tid & 3) << 4) + (un << 3);
            const uint4 w0 = *(const uint4*)(asl + (un * 2) * 8192);
            const uint4 w1 = *(const uint4*)(asl + (un * 2 + 1) * 8192);
            const float4 fA = *(const float4*)&s_f2[tch + jl];
            const float4 fB = *(const float4*)&s_f2[tch + jl + 4];
            const unsigned bb[8] = {w0.x, w0.y, w0.z, w0.w, w1.x, w1.y, w1.z, w1.w};
            const float fs[8]    = {fA.x, fA.y, fA.z, fA.w, fB.x, fB.y, fB.z, fB.w};
            unsigned pn[8];
#pragma unroll
            for (int e = 0; e < 8; e++) {
                unsigned sel = (fs[e] >= thr) ? 0x00003C00u : 0x3C000000u;
                pn[e] = (bb[e] != 0u) ? sel : 0u;
            }
            uint4 wp4, wn4;
            wp4.x = prmt(pn[0], pn[1], 0x5410u); wn4.x = prmt(pn[0], pn[1], 0x7632u);
            wp4.y = prmt(pn[2], pn[3], 0x5410u); wn4.y = prmt(pn[2], pn[3], 0x7632u);
            wp4.z = prmt(pn[4], pn[5], 0x5410u); wn4.z = prmt(pn[4], pn[5], 0x7632u);
            wp4.w = prmt(pn[6], pn[7], 0x5410u); wn4.w = prmt(pn[6], pn[7], 0x7632u);
            const uint32_t off = rb + (((uint32_t)(jl << 1)) ^ rsw);
            *(uint4*)(mdst + off)          = wp4;
            *(uint4*)(mdst + 16384 + off)  = wn4;
        }
    };

    // ---- B prefetch (chunk c -> buffer bb): 32KB UV + 1KB z ----
    auto prefetch_B = [&](int c, int bb) {
        const int nc = (hh << 6) + c;
        const uint32_t dstb = bbuf_u + (uint32_t)bb * BBUF;
        const char* srcb = (const char*)g_UVT2 + (size_t)nc * 16384;
#pragma unroll
        for (int pass = 0; pass < 4; pass++) {
            int u = tid + pass * 512;
            int m = u >> 10;
            uint32_t off = (uint32_t)(u & 1023) << 4;
            cp_async16(dstb + (uint32_t)m * BTILE + off, srcb + (size_t)m * 2097152 + off);
        }
        if (tid < 64)
            cp_async16(dstb + 2u * BTILE + (uint32_t)tid * 16u,
                       (const char*)g_ZT + (size_t)nc * 1024 + tid * 16);
    };

    // ---- prologue ----
    prefetch_adj(0);
    prefetch_adj(1);
    prefetch_B(0, 0);
    CP_COMMIT();                 // g1: adj0, adj1, B0, z0
    prefetch_B(1, 1);
    CP_COMMIT();                 // g2: B1, z1
    CP_WAIT1();                  // g1 complete: adj0 (own), B0
    __syncthreads();             // B0 visible to all
    build_masks(0, 0);

    for (int t = 0; t < 64; t++) {
        CP_WAIT2();              // B[t] (and older) complete
        __syncthreads();         // masks[t] + B[t] visible

        if (t + 2 < 64) prefetch_adj(t + 2);
        CP_COMMIT();             // G1(t): adj[t+2]

        const uint32_t mpos = dbase + (uint32_t)(t & 1) * MASKBUF;
        const uint32_t mneg = mpos + 16384u;
        const uint32_t bufb = bbuf_u + (uint32_t)(t & 1) * BBUF;

#pragma unroll
        for (int ks = 0; ks < 4; ks++) {
            const uint32_t joff = ((uint32_t)ks << 5) | akh;
            uint32_t ap0[4], ap1[4], an0[4], an1[4];
            LDSM_X4(ap0[0], ap0[1], ap0[2], ap0[3], mpos + arow0 + (joff ^ asw0));
            LDSM_X4(ap1[0], ap1[1], ap1[2], ap1[3], mpos + arow1 + (joff ^ asw1));
            LDSM_X4(an0[0], an0[1], an0[2], an0[3], mneg + arow0 + (joff ^ asw0));
            LDSM_X4(an1[0], an1[1], an1[2], an1[3], mneg + arow1 + (joff ^ asw1));

            {
                uint32_t b0[4], b1[4];
                const uint32_t pb = bufb + brow;
                LDSM_X4(b0[0], b0[1], b0[2], b0[3], pb + ((((uint32_t)ks << 5) | 0u)  ^ bsw));
                LDSM_X4(b1[0], b1[1], b1[2], b1[3], pb + ((((uint32_t)ks << 5) | 16u) ^ bsw));
#pragma unroll
                for (int nt = 0; nt < 4; nt++) {
                    MMA16816(dp[0][nt], ap0[0], ap0[1], ap0[2], ap0[3], b0[nt], b1[nt]);
                    MMA16816(dp[1][nt], ap1[0], ap1[1], ap1[2], ap1[3], b0[nt], b1[nt]);
                }
            }
            {
                uint32_t b0[4], b1[4];
                const uint32_t pb = bufb + BTILE + brow;
                LDSM_X4(b0[0], b0[1], b0[2], b0[3], pb + ((((uint32_t)ks << 5) | 0u)  ^ bsw));
                LDSM_X4(b1[0], b1[1], b1[2], b1[3], pb + ((((uint32_t)ks << 5) | 16u) ^ bsw));
#pragma unroll
                for (int nt = 0; nt < 4; nt++) {
                    MMA16816(dn[0][nt], an0[0], an0[1], an0[2], an0[3], b0[nt], b1[nt]);
                    MMA16816(dn[1][nt], an1[0], an1[1], an1[2], an1[3], b0[nt], b1[nt]);
                }
            }
            if (diag) {
                const uint32_t zk = ((uint32_t)ks << 5) + zkb;
                const uint32_t a0 = bufb + zrow + (zk ^ zsw);
                const uint32_t a1 = bufb + zrow + ((zk + 16u) ^ zsw);
                uint32_t bz0, bz1;
                asm volatile("ld.shared.b32 %0, [%1];" : "=r"(bz0) : "r"(a0));
                asm volatile("ld.shared.b32 %0, [%1];" : "=r"(bz1) : "r"(a1));
                MMA16816(dzp[0], ap0[0], ap0[1], ap0[2], ap0[3], bz0, bz1);
                MMA16816(dzp[1], ap1[0], ap1[1], ap1[2], ap1[3], bz0, bz1);
                MMA16816(dzn[0], an0[0], an0[1], an0[2], an0[3], bz0, bz1);
                MMA16816(dzn[1], an1[0], an1[1], an1[2], an1[3], bz0, bz1);
            }
        }

        CP_WAIT2();              // own adj[t+1] cp.asyncs complete (reader == issuer)
        if (t < 63) build_masks(t + 1, (t + 1) & 1);
        if (t + 2 < 64) prefetch_B(t + 2, t & 1);
        CP_COMMIT();             // G2(t): B[t+2]
    }

    // ---- write raw partials ----
    float* pdst = g_pp + (size_t)hh * (NROWS * NOUT);
    float* ndst = g_pn + (size_t)hh * (NROWS * NOUT);
#pragma unroll
    for (int mt = 0; mt < 2; mt++) {
        const int r0 = i0 + ib + mt * 16 + (lane >> 2);
        const int r1 = r0 + 8;
#pragma unroll
        for (int nt = 0; nt < 4; nt++) {
            const int c = cb + nt * 8 + ((lane & 3) << 1);
            *(float2*)&pdst[(size_t)r0 * NOUT + c] = make_float2(dp[mt][nt][0], dp[mt][nt][1]);
            *(float2*)&pdst[(size_t)r1 * NOUT + c] = make_float2(dp[mt][nt][2], dp[mt][nt][3]);
            *(float2*)&ndst[(size_t)r0 * NOUT + c] = make_float2(dn[mt][nt][0], dn[mt][nt][1]);
            *(float2*)&ndst[(size_t)r1 * NOUT + c] = make_float2(dn[mt][nt][2], dn[mt][nt][3]);
        }
    }
    if (diag) {
#pragma unroll
        for (int mt = 0; mt < 2; mt++) {
            const int r0 = i0 + ib + mt * 16 + (lane >> 2);
            if ((lane & 3) == 0) {
                g_zu[hh * NROWS + r0]     = dzp[mt][0];
                g_zu[hh * NROWS + r0 + 8] = dzp[mt][2];
                g_zv[hh * NROWS + r0]     = dzn[mt][1];
                g_zv[hh * NROWS + r0 + 8] = dzn[mt][3];
            }
        }
    }

    // ---- device-wide barrier ----
    __threadfence();
    __syncthreads();
    if (tid == 0) {
        unsigned t0 = atomicAdd(&g_cnt, 1u);
        unsigned target = ((t0 >> 7) + 1u) << 7;
        unsigned cur;
        do {
            asm volatile("ld.acquire.gpu.u32 %0, [%1];" : "=r"(cur) : "l"(&g_cnt));
            if (cur < target) __nanosleep(128);
        } while (cur < target);
    }
    __syncthreads();

    // ---- combine ----
    {
        const int rbase = blockIdx.x * 64;
#pragma unroll
        for (int it = 0; it < 4; it++) {
            int u = tid + it * 512;
            int r = rbase + (u >> 5);
            int c = (u & 31) * 4;
            float A = g_A[r], Cc = g_C[r];
            float z = A * (g_zu[r] + g_zu[NROWS + r]) + Cc * (g_zv[r] + g_zv[NROWS + r]);
            float zi = 1.f / z;
            const float4 p0 = *(const float4*)&g_pp[(size_t)r * NOUT + c];
            const float4 p1 = *(const float4*)&g_pp[(size_t)(NROWS + r) * NOUT + c];
            const float4 n0 = *(const float4*)&g_pn[(size_t)r * NOUT + c];
            const float4 n1 = *(const float4*)&g_pn[(size_t)(NROWS + r) * NOUT + c];
            float4 o;
            o.x = (A * (p0.x + p1.x) + Cc * (n0.x + n1.x)) * zi;
            o.y = (A * (p0.y + p1.y) + Cc * (n0.y + n1.y)) * zi;
            o.z = (A * (p0.z + p1.z) + Cc * (n0.z + n1.z)) * zi;
            o.w = (A * (p0.w + p1.w) + Cc * (n0.w + n1.w)) * zi;
            *(float4*)&out[(size_t)r * NOUT + c] = o;
        }
    }
}

// ---------------- launcher ----------------
extern "C" void kernel_launch(void* const* d_in, const int* in_sizes, int n_in,
                              void* d_out, int out_size) {
    const float* h = nullptr; const int* adj = nullptr; const float* W = nullptr; const float* a = nullptr;
    for (int k = 0; k < n_in; k++) {
        switch (in_sizes[k]) {
            case NROWS * INP:   h   = (const float*)d_in[k]; break;
            case NROWS * NROWS: adj = (const int*)d_in[k];   break;
            case INP * NOUT:    W   = (const float*)d_in[k]; break;
            case 2 * NOUT:      a   = (const float*)d_in[k]; break;
            default: break;
        }
    }
    float* out = (float*)d_out;

    cudaFuncSetAttribute(k4_hmma, cudaFuncAttributeMaxDynamicSharedMemorySize, DYNSMEM);

    kA     <<<128, 256>>>(h, W, a);
    k4_hmma<<<128, 512, DYNSMEM>>>(adj, out);
}